// round 15
// baseline (speedup 1.0000x reference)
#include <cuda_runtime.h>
#include <cuda_fp16.h>
#include <cstdint>

#define HID 51
#define SEQL 999
#define NTHREADS 256     // 7 MMA warps + 1 aux warp
#define NBLOCKS 512      // 8 batch rows per CTA -> up to 4 CTAs per SM

// A fragments (h fp16): [parity][kc] x 512B (lane*16 holds a0..a3, M=16 rows,
// rows 8..15 are always-zero padding)
struct SM {
    uint8_t abuf[2][4][512];
};
__shared__ SM sm;

__device__ __forceinline__ float tanh_a(float x) {
    float y; asm("tanh.approx.f32 %0, %1;" : "=f"(y) : "f"(x)); return y;
}
__device__ __forceinline__ float sigm(float x) {
    return fmaf(tanh_a(0.5f * x), 0.5f, 0.5f);
}
__device__ __forceinline__ void mma_fp16(float* d, const uint32_t* a, const uint32_t* b) {
    asm volatile("mma.sync.aligned.m16n8k16.row.col.f32.f16.f16.f32 "
                 "{%0,%1,%2,%3}, {%4,%5,%6,%7}, {%8,%9}, {%0,%1,%2,%3};"
                 : "+f"(d[0]), "+f"(d[1]), "+f"(d[2]), "+f"(d[3])
                 : "r"(a[0]), "r"(a[1]), "r"(a[2]), "r"(a[3]), "r"(b[0]), "r"(b[1]));
}
// byte offset of element (row rp 0..15, col kk 0..15) inside a 512B fp16 A frag
__device__ __forceinline__ int frag_off(int rp, int kk) {
    int lane = (rp & 7) * 4 + ((kk & 7) >> 1);
    int reg  = ((rp >> 3) & 1) + 2 * ((kk >> 3) & 1);
    return lane * 16 + reg * 4 + (kk & 1) * 2;
}
__device__ __forceinline__ uint32_t pkh2(float v0, float v1) {
    __half2 h = __floats2half2_rn(v0, v1);
    return *(uint32_t*)&h;
}

__global__ __launch_bounds__(NTHREADS, 4)
void lstm_fp16_kernel(const float* __restrict__ input,
                      const float* __restrict__ W_ih,
                      const float* __restrict__ W_hh,
                      const float* __restrict__ b_ih,
                      const float* __restrict__ b_hh,
                      const float* __restrict__ W_fc,
                      const float* __restrict__ b_fc,
                      float* __restrict__ out)
{
    const int tid = threadIdx.x;
    const int w   = tid >> 5;
    const int l   = tid & 31;
    const int r4  = l & 3;
    const int q   = l >> 2;
    const int bbase = blockIdx.x * 8;

    // ---- zero A buffers (rows 8..15 stay zero forever) ----
    {
        uint32_t* p = (uint32_t*)sm.abuf;
        for (int i = tid; i < (int)(sizeof(sm.abuf) / 4); i += NTHREADS) p[i] = 0;
    }
    __syncthreads();
    // bias col (k=52 -> kc3,kk4) = 1.0 both parities; x(0) (k=51 -> kc3,kk3) parity 0
    if (tid < 8) {
        int rp = tid;
        for (int par = 0; par < 2; par++)
            *(uint16_t*)&sm.abuf[par][3][frag_off(rp, 4)] = 0x3C00; // fp16 1.0
        float x = input[(size_t)(bbase + tid) * SEQL];
        *(__half*)&sm.abuf[0][3][frag_off(rp, 3)] = __float2half_rn(x);
    }

    // ---- weight fragments (fp16, 1-term) into registers ----
    // B-col q of n-tile nt in warp w: p = nt>>1, half = nt&1, u = q>>1, e2 = q&1;
    // unit j = w*8 + p*4 + u; gate = half*2 + e2 (i,f even nt; g,o odd nt);
    // original row = gate*51 + j. FC col at warp 6, p=1, u=3, gate=0.
    uint32_t wh[4][4][2];
    if (w < 7) {
        #pragma unroll
        for (int kc = 0; kc < 4; kc++)
        #pragma unroll
        for (int nt = 0; nt < 4; nt++)
        #pragma unroll
        for (int e = 0; e < 2; e++) {
            int p = nt >> 1, half = nt & 1;
            int u = q >> 1, e2 = q & 1;
            int j = w * 8 + p * 4 + u;
            int gate = half * 2 + e2;
            int k0 = kc * 16 + r4 * 2 + e * 8;
            float v0 = 0.0f, v1 = 0.0f;
            #pragma unroll
            for (int hlf = 0; hlf < 2; hlf++) {
                int k = k0 + hlf;
                float v = 0.0f;
                if (j < HID) {
                    int row = gate * HID + j;
                    if (k < HID)       v = W_hh[row * HID + k];
                    else if (k == 51)  v = W_ih[row];
                    else if (k == 52)  v = b_ih[row] + b_hh[row];
                } else if (w == 6 && p == 1 && u == 3 && gate == 0) { // FC col
                    if (k < HID)       v = W_fc[k];
                    else if (k == 52)  v = b_fc[0];
                }
                if (hlf) v1 = v; else v0 = v;
            }
            wh[kc][nt][e] = pkh2(v0, v1);
        }
    }
    __syncthreads();

    // c-state (fp32): units j = w*8 + p*4 + r4 (p=0,1), single batch row q
    float cst[2] = {0.0f, 0.0f};

    // aux warp prefetch register: x(t+1)
    float xnext = 0.0f;
    if (w == 7 && l < 8 && SEQL > 1)
        xnext = input[(size_t)(bbase + l) * SEQL + 1];

    for (int t = 0; t < SEQL; t++) {
        const int par = t & 1;
        if (w < 7) {
            // ---- phase 1: 16 HMMA (fp16 1-term, 4 n-tiles) ----
            float acc[4][4];
            #pragma unroll
            for (int nt = 0; nt < 4; nt++)
            #pragma unroll
            for (int i = 0; i < 4; i++) acc[nt][i] = 0.0f;

            #pragma unroll
            for (int kc = 0; kc < 4; kc++) {
                uint32_t A[4];
                *(uint4*)A = *(const uint4*)&sm.abuf[par][kc][l * 16];
                #pragma unroll
                for (int nt = 0; nt < 4; nt++)
                    mma_fp16(acc[nt], A, wh[kc][nt]);
            }

            // ---- phase 2: shuffle-free LSTM update (row q only; rows 8-15 pad) ----
            #pragma unroll
            for (int p = 0; p < 2; p++) {
                int j = w * 8 + p * 4 + r4;
                bool real = (w < 6) || (p == 0 && r4 < 3);
                if (real) {
                    float gi = acc[2 * p][0];
                    float gf = acc[2 * p][1];
                    float gG = acc[2 * p + 1][0];
                    float gO = acc[2 * p + 1][1];
                    float cn = fmaf(sigm(gf), cst[p], sigm(gi) * tanh_a(gG));
                    cst[p] = cn;
                    float h = sigm(gO) * tanh_a(cn);
                    *(__half*)&sm.abuf[par ^ 1][j >> 4][frag_off(q, j & 15)] =
                        __float2half_rn(h);
                }
            }
            // ---- y(t-1) from FC column (warp 6, r4==3, row q) ----
            if (w == 6 && r4 == 3 && t > 0)
                out[(size_t)(bbase + q) * SEQL + (t - 1)] = acc[2][0];
        } else if (l < 8) {
            // ---- aux warp: stage x(t+1) (prefetched), prefetch x(t+2) ----
            if (t + 1 < SEQL)
                *(__half*)&sm.abuf[par ^ 1][3][frag_off(l, 3)] = __float2half_rn(xnext);
            if (t + 2 < SEQL)
                xnext = input[(size_t)(bbase + l) * SEQL + t + 2];
        }
        __syncthreads();
    }

    // ---- epilogue: y(SEQL-1) via FC-column MMA on h(SEQL-1) (warp 6) ----
    if (w == 6) {
        const int par = SEQL & 1;
        float acc1[4] = {0.0f, 0.0f, 0.0f, 0.0f};
        #pragma unroll
        for (int kc = 0; kc < 4; kc++) {
            uint32_t A[4];
            *(uint4*)A = *(const uint4*)&sm.abuf[par][kc][l * 16];
            mma_fp16(acc1, A, wh[kc][2]);
        }
        if (r4 == 3)
            out[(size_t)(bbase + q) * SEQL + (SEQL - 1)] = acc1[0];
    }
}

extern "C" void kernel_launch(void* const* d_in, const int* in_sizes, int n_in,
                              void* d_out, int out_size) {
    const float* input = (const float*)d_in[0];
    const float* W_ih  = (const float*)d_in[1];
    const float* W_hh  = (const float*)d_in[2];
    const float* b_ih  = (const float*)d_in[3];
    const float* b_hh  = (const float*)d_in[4];
    const float* W_fc  = (const float*)d_in[5];
    const float* b_fc  = (const float*)d_in[6];
    // d_in[7] = future (static 0) — ignored.

    lstm_fp16_kernel<<<NBLOCKS, NTHREADS>>>(
        input, W_ih, W_hh, b_ih, b_hh, W_fc, b_fc, (float*)d_out);
}

// round 17
// speedup vs baseline: 1.6215x; 1.6215x over previous
#include <cuda_runtime.h>
#include <cuda_fp16.h>
#include <cstdint>

#define HID 51
#define SEQL 999
#define BATCH 4096
#define BTILE 14         // batch rows per CTA (tile rows 14,15 = zero pad)
#define NTHREADS 256     // 7 MMA warps + 1 aux warp
#define NBLOCKS 293      // ceil(4096/14) -> every SM <= 2 CTAs, balanced

// A fragments (h fp16): [parity][kc] x 512B (lane*16 holds a0..a3, M=16 rows)
struct SM {
    uint8_t abuf[2][4][512];
};
__shared__ SM sm;

__device__ __forceinline__ float tanh_a(float x) {
    float y; asm("tanh.approx.f32 %0, %1;" : "=f"(y) : "f"(x)); return y;
}
__device__ __forceinline__ float sigm(float x) {
    return fmaf(tanh_a(0.5f * x), 0.5f, 0.5f);
}
__device__ __forceinline__ void mma_fp16(float* d, const uint32_t* a, const uint32_t* b) {
    asm volatile("mma.sync.aligned.m16n8k16.row.col.f32.f16.f16.f32 "
                 "{%0,%1,%2,%3}, {%4,%5,%6,%7}, {%8,%9}, {%0,%1,%2,%3};"
                 : "+f"(d[0]), "+f"(d[1]), "+f"(d[2]), "+f"(d[3])
                 : "r"(a[0]), "r"(a[1]), "r"(a[2]), "r"(a[3]), "r"(b[0]), "r"(b[1]));
}
// byte offset of element (row rp 0..15, col kk 0..15) inside a 512B fp16 A frag
__device__ __forceinline__ int frag_off(int rp, int kk) {
    int lane = (rp & 7) * 4 + ((kk & 7) >> 1);
    int reg  = ((rp >> 3) & 1) + 2 * ((kk >> 3) & 1);
    return lane * 16 + reg * 4 + (kk & 1) * 2;
}
__device__ __forceinline__ uint32_t pkh2(float v0, float v1) {
    __half2 h = __floats2half2_rn(v0, v1);
    return *(uint32_t*)&h;
}

__global__ __launch_bounds__(NTHREADS, 2)
void lstm_fp16_kernel(const float* __restrict__ input,
                      const float* __restrict__ W_ih,
                      const float* __restrict__ W_hh,
                      const float* __restrict__ b_ih,
                      const float* __restrict__ b_hh,
                      const float* __restrict__ W_fc,
                      const float* __restrict__ b_fc,
                      float* __restrict__ out)
{
    const int tid = threadIdx.x;
    const int w   = tid >> 5;
    const int l   = tid & 31;
    const int r4  = l & 3;
    const int q   = l >> 2;
    const int bbase = blockIdx.x * BTILE;

    // ---- zero A buffers (pad rows stay zero only until phase2 writes them;
    //      pad-row h values are garbage-but-contained: rows are independent) ----
    {
        uint32_t* p = (uint32_t*)sm.abuf;
        for (int i = tid; i < (int)(sizeof(sm.abuf) / 4); i += NTHREADS) p[i] = 0;
    }
    __syncthreads();
    // bias col (k=52 -> kc3,kk4) = 1.0 both parities; x(0) (k=51 -> kc3,kk3) parity 0
    if (tid < BTILE && bbase + tid < BATCH) {
        int rp = tid;
        for (int par = 0; par < 2; par++)
            *(uint16_t*)&sm.abuf[par][3][frag_off(rp, 4)] = 0x3C00; // fp16 1.0
        float x = input[(size_t)(bbase + tid) * SEQL];
        *(__half*)&sm.abuf[0][3][frag_off(rp, 3)] = __float2half_rn(x);
    }

    // ---- weight fragments (fp16, 1-term) into registers ----
    // B-col q of n-tile nt in warp w: p = nt>>1, half = nt&1, u = q>>1, e2 = q&1;
    // unit j = w*8 + p*4 + u; gate = half*2 + e2 (i,f even nt; g,o odd nt);
    // original row = gate*51 + j. FC col at warp 6, p=1, u=3, gate=0.
    uint32_t wh[4][4][2];
    if (w < 7) {
        #pragma unroll
        for (int kc = 0; kc < 4; kc++)
        #pragma unroll
        for (int nt = 0; nt < 4; nt++)
        #pragma unroll
        for (int e = 0; e < 2; e++) {
            int p = nt >> 1, half = nt & 1;
            int u = q >> 1, e2 = q & 1;
            int j = w * 8 + p * 4 + u;
            int gate = half * 2 + e2;
            int k0 = kc * 16 + r4 * 2 + e * 8;
            float v0 = 0.0f, v1 = 0.0f;
            #pragma unroll
            for (int hlf = 0; hlf < 2; hlf++) {
                int k = k0 + hlf;
                float v = 0.0f;
                if (j < HID) {
                    int row = gate * HID + j;
                    if (k < HID)       v = W_hh[row * HID + k];
                    else if (k == 51)  v = W_ih[row];
                    else if (k == 52)  v = b_ih[row] + b_hh[row];
                } else if (w == 6 && p == 1 && u == 3 && gate == 0) { // FC col
                    if (k < HID)       v = W_fc[k];
                    else if (k == 52)  v = b_fc[0];
                }
                if (hlf) v1 = v; else v0 = v;
            }
            wh[kc][nt][e] = pkh2(v0, v1);
        }
    }
    __syncthreads();

    // c-state (fp32): units j = w*8 + p*4 + r4 (p=0,1) x batch rows q, q+8
    float cst[4] = {0.0f, 0.0f, 0.0f, 0.0f};

    // row validity for this thread's two D rows (q and q+8)
    const bool rowlo_ok = (bbase + q < BATCH);                       // q <= 7 < BTILE
    const bool rowhi_ok = (q + 8 < BTILE) && (bbase + q + 8 < BATCH);

    // aux warp prefetch register: x(t+1)
    float xnext = 0.0f;
    const bool aux_ok = (w == 7) && (l < BTILE) && (bbase + l < BATCH);
    if (aux_ok && SEQL > 1)
        xnext = input[(size_t)(bbase + l) * SEQL + 1];

    for (int t = 0; t < SEQL; t++) {
        const int par = t & 1;
        if (w < 7) {
            // ---- phase 1: 16 HMMA (fp16 1-term, 4 n-tiles) ----
            float acc[4][4];
            #pragma unroll
            for (int nt = 0; nt < 4; nt++)
            #pragma unroll
            for (int i = 0; i < 4; i++) acc[nt][i] = 0.0f;

            #pragma unroll
            for (int kc = 0; kc < 4; kc++) {
                uint32_t A[4];
                *(uint4*)A = *(const uint4*)&sm.abuf[par][kc][l * 16];
                #pragma unroll
                for (int nt = 0; nt < 4; nt++)
                    mma_fp16(acc[nt], A, wh[kc][nt]);
            }

            // ---- phase 2: shuffle-free LSTM update (gate quad is thread-local) ----
            #pragma unroll
            for (int p = 0; p < 2; p++) {
                int j = w * 8 + p * 4 + r4;
                bool real = (w < 6) || (p == 0 && r4 < 3);
                if (real) {
                    #pragma unroll
                    for (int rr = 0; rr < 2; rr++) {
                        float gi = acc[2 * p][rr * 2 + 0];
                        float gf = acc[2 * p][rr * 2 + 1];
                        float gG = acc[2 * p + 1][rr * 2 + 0];
                        float gO = acc[2 * p + 1][rr * 2 + 1];
                        int ci = p * 2 + rr;
                        float cn = fmaf(sigm(gf), cst[ci], sigm(gi) * tanh_a(gG));
                        cst[ci] = cn;
                        float h = sigm(gO) * tanh_a(cn);
                        *(__half*)&sm.abuf[par ^ 1][j >> 4][frag_off(q + rr * 8, j & 15)] =
                            __float2half_rn(h);
                    }
                }
            }
            // ---- y(t-1) from FC column (warp 6, r4==3, D col 6 of nt=2) ----
            if (w == 6 && r4 == 3 && t > 0) {
                if (rowlo_ok)
                    out[(size_t)(bbase + q) * SEQL + (t - 1)]     = acc[2][0];
                if (rowhi_ok)
                    out[(size_t)(bbase + q + 8) * SEQL + (t - 1)] = acc[2][2];
            }
        } else if (aux_ok) {
            // ---- aux warp: stage x(t+1) (prefetched), prefetch x(t+2) ----
            if (t + 1 < SEQL)
                *(__half*)&sm.abuf[par ^ 1][3][frag_off(l, 3)] = __float2half_rn(xnext);
            if (t + 2 < SEQL)
                xnext = input[(size_t)(bbase + l) * SEQL + t + 2];
        }
        __syncthreads();
    }

    // ---- epilogue: y(SEQL-1) via FC-column MMA on h(SEQL-1) (warp 6) ----
    if (w == 6) {
        const int par = SEQL & 1;
        float acc1[4] = {0.0f, 0.0f, 0.0f, 0.0f};
        #pragma unroll
        for (int kc = 0; kc < 4; kc++) {
            uint32_t A[4];
            *(uint4*)A = *(const uint4*)&sm.abuf[par][kc][l * 16];
            mma_fp16(acc1, A, wh[kc][2]);
        }
        if (r4 == 3) {
            if (rowlo_ok)
                out[(size_t)(bbase + q) * SEQL + (SEQL - 1)]     = acc1[0];
            if (rowhi_ok)
                out[(size_t)(bbase + q + 8) * SEQL + (SEQL - 1)] = acc1[2];
        }
    }
}

extern "C" void kernel_launch(void* const* d_in, const int* in_sizes, int n_in,
                              void* d_out, int out_size) {
    const float* input = (const float*)d_in[0];
    const float* W_ih  = (const float*)d_in[1];
    const float* W_hh  = (const float*)d_in[2];
    const float* b_ih  = (const float*)d_in[3];
    const float* b_hh  = (const float*)d_in[4];
    const float* W_fc  = (const float*)d_in[5];
    const float* b_fc  = (const float*)d_in[6];
    // d_in[7] = future (static 0) — ignored.

    lstm_fp16_kernel<<<NBLOCKS, NTHREADS>>>(
        input, W_ih, W_hh, b_ih, b_hh, W_fc, b_fc, (float*)d_out);
}